// round 6
// baseline (speedup 1.0000x reference)
#include <cuda_runtime.h>
#include <math.h>
#include <stdint.h>

#define NPTS 3072
#define NT   1024
#define EPB  3          // NPTS / NT
#define NCLS 10

static_assert(NT * EPB == NPTS, "partition");

// 3072x3072 fp32 distance matrix (37.7MB, L2-resident)
__device__ float g_D[(size_t)NPTS * NPTS];

// cold merge-phase state (device globals; block-internal visibility via __syncthreads)
__device__ int   g_cc[NPTS];
__device__ int   g_counts[NPTS];
__device__ float g_cenx[NPTS], g_ceny[NPTS], g_cenz[NPTS];
__device__ int   g_order[NPTS];
__device__ int   g_cmap[NPTS];
__device__ int   g_keep[NPTS];

// ---------------- Kernel 1: chip-wide pairwise distances ----------------
__global__ void dist_kernel(const float* __restrict__ pts) {
    int i = blockIdx.x;
    float xi = pts[3 * i + 0], yi = pts[3 * i + 1], zi = pts[3 * i + 2];
    for (int j = threadIdx.x; j < NPTS; j += blockDim.x) {
        float dx = __fsub_rn(pts[3 * j + 0], xi);
        float dy = __fsub_rn(pts[3 * j + 1], yi);
        float dz = __fsub_rn(pts[3 * j + 2], zi);
        float s2 = __fadd_rn(__fadd_rn(__fmul_rn(dx, dx), __fmul_rn(dy, dy)),
                             __fmul_rn(dz, dz));
        g_D[(size_t)i * NPTS + j] = __fsqrt_rn(s2);
    }
}

// ---------------- static-smem hot state: <= 48KB ----------------
struct SMh {
    unsigned long long pB[2][32];      // 512   (8B aligned first)
    float px[NPTS], py[NPTS], pz[NPTS];// 36864
    float pA[2][7][32];                // 1792
    short dl[NPTS];                    // 6144
    signed char lbl[NPTS];             // 3072
    float amdm[NCLS], amdh[NCLS], r2[NCLS]; // 120
};

__device__ __forceinline__ unsigned long long u64min(unsigned long long a,
                                                     unsigned long long b) {
    return a < b ? a : b;
}

// JAX acos: acos(x) = x!=-1 ? 2*atan2(sqrt(1-x*x), 1+x) : pi
__device__ __forceinline__ float xla_acosf(float v) {
    const float PI_F = __int_as_float(0x40490fdb);
    if (v == -1.0f) return PI_F;
    float s = __fsqrt_rn(__fsub_rn(1.0f, __fmul_rn(v, v)));
    float c = __fadd_rn(1.0f, v);
    return __fmul_rn(2.0f, atan2f(s, c));
}

__global__ __launch_bounds__(NT, 1)
void cluster_kernel(const float* __restrict__ pts, const int* __restrict__ lblg,
                    const float* __restrict__ anc, float* __restrict__ out) {
    __shared__ SMh sm;
    const int tid  = threadIdx.x;
    const int lane = tid & 31;
    const int wid  = tid >> 5;
    const float INF  = __int_as_float(0x7f800000);
    const float NINF = __int_as_float(0xff800000);
    const float ANGLE_THR = __int_as_float(0x3fc90fdb);   // fp32(pi/2)

    // ---- init state ----
    for (int j = tid; j < NPTS; j += NT) {
        sm.px[j] = pts[3 * j + 0];
        sm.py[j] = pts[3 * j + 1];
        sm.pz[j] = pts[3 * j + 2];
        sm.lbl[j] = (signed char)lblg[j];
        sm.dl[j]  = (j == 0) ? 0 : -1;
        g_cc[j]   = -1;
        g_cmap[j] = j;
    }
    if (tid < NCLS) {
        float l = anc[3 * tid + 0], w = anc[3 * tid + 1], h = anc[3 * tid + 2];
        sm.amdm[tid] = fmaxf(l, w);
        sm.amdh[tid] = h;
        float n2 = __fadd_rn(__fadd_rn(__fmul_rn(l, l), __fmul_rn(w, w)),
                             __fmul_rn(h, h));
        sm.r2[tid] = __fdiv_rn(__fsqrt_rn(n2), 2.0f);
    }
    __syncthreads();

    // ---- main sequential greedy loop: 3071 steps ----
    int cur = 0, lab = 0;
    for (int step = 0; step < NPTS - 1; ++step) {
        const int buf = step & 1;
        const int cls = (int)sm.lbl[cur];
        const float pcx = sm.px[cur], pcy = sm.py[cur], pcz = sm.pz[cur];
        const float npc = __fsqrt_rn(__fadd_rn(
            __fadd_rn(__fmul_rn(pcx, pcx), __fmul_rn(pcy, pcy)),
            __fmul_rn(pcz, pcz)));
        if (tid == 0) {
            if (g_cc[lab] < 0) g_cc[lab] = cls;
        }
        const float* Drow = g_D + (size_t)cur * NPTS;

        // Phase A: loads + partial (dmin, dmax, centre-sum, count, angle-max)
        float djv[EPB];
        int   stv[EPB];
        float dmin = INF, dmax = NINF, amax = NINF;
        float sx = 0.f, sy = 0.f, sz = 0.f, cf = 0.f;
#pragma unroll
        for (int k = 0; k < EPB; ++k) {
            const int j = tid + k * NT;
            float d  = __ldg(Drow + j);
            int   dv = (int)sm.dl[j];
            djv[k] = d;
            stv[k] = dv;
            if (dv == -1) { dmin = fminf(dmin, d); dmax = fmaxf(dmax, d); }
            if (dv == lab) {
                sx = __fadd_rn(sx, sm.px[j]);
                sy = __fadd_rn(sy, sm.py[j]);
                sz = __fadd_rn(sz, sm.pz[j]);
                cf = __fadd_rn(cf, 1.0f);
                float ddx = __fsub_rn(sm.px[j], pcx);
                float ddy = __fsub_rn(sm.py[j], pcy);
                float ddz = __fsub_rn(sm.pz[j], pcz);
                float dot = __fadd_rn(__fadd_rn(__fmul_rn(pcx, ddx),
                                                __fmul_rn(pcy, ddy)),
                                      __fmul_rn(pcz, ddz));
                dot = -dot;
                float den = __fadd_rn(__fmul_rn(npc, d), 1e-8f);
                float v = __fdiv_rn(dot, den);
                v = fminf(fmaxf(v, -1.0f), 1.0f);
                amax = fmaxf(amax, xla_acosf(v));
            }
        }
#pragma unroll
        for (int o = 16; o; o >>= 1) {
            dmin = fminf(dmin, __shfl_xor_sync(0xffffffffu, dmin, o));
            dmax = fmaxf(dmax, __shfl_xor_sync(0xffffffffu, dmax, o));
            amax = fmaxf(amax, __shfl_xor_sync(0xffffffffu, amax, o));
            sx   = __fadd_rn(sx, __shfl_xor_sync(0xffffffffu, sx, o));
            sy   = __fadd_rn(sy, __shfl_xor_sync(0xffffffffu, sy, o));
            sz   = __fadd_rn(sz, __shfl_xor_sync(0xffffffffu, sz, o));
            cf   = __fadd_rn(cf, __shfl_xor_sync(0xffffffffu, cf, o));
        }
        if (lane == 0) {
            sm.pA[buf][0][wid] = dmin; sm.pA[buf][1][wid] = dmax;
            sm.pA[buf][2][wid] = sx;   sm.pA[buf][3][wid] = sy;
            sm.pA[buf][4][wid] = sz;   sm.pA[buf][5][wid] = cf;
            sm.pA[buf][6][wid] = amax;
        }
        __syncthreads();   // sync 1

        dmin = sm.pA[buf][0][lane]; dmax = sm.pA[buf][1][lane];
        sx = sm.pA[buf][2][lane]; sy = sm.pA[buf][3][lane];
        sz = sm.pA[buf][4][lane]; cf = sm.pA[buf][5][lane];
        amax = sm.pA[buf][6][lane];
#pragma unroll
        for (int o = 16; o; o >>= 1) {
            dmin = fminf(dmin, __shfl_xor_sync(0xffffffffu, dmin, o));
            dmax = fmaxf(dmax, __shfl_xor_sync(0xffffffffu, dmax, o));
            amax = fmaxf(amax, __shfl_xor_sync(0xffffffffu, amax, o));
            sx   = __fadd_rn(sx, __shfl_xor_sync(0xffffffffu, sx, o));
            sy   = __fadd_rn(sy, __shfl_xor_sync(0xffffffffu, sy, o));
            sz   = __fadd_rn(sz, __shfl_xor_sync(0xffffffffu, sz, o));
            cf   = __fadd_rn(cf, __shfl_xor_sync(0xffffffffu, cf, o));
        }
        const float ccx = __fdiv_rn(sx, cf);
        const float ccy = __fdiv_rn(sy, cf);
        const float ccz = __fdiv_rn(sz, cf);
        const float s   = __fadd_rn(__fsub_rn(dmax, dmin), 1e-8f);

        // Phase B: argmin over unvisited of (dcost + lcost), first-index ties
        unsigned long long key = ~0ull;
#pragma unroll
        for (int k = 0; k < EPB; ++k) {
            if (stv[k] == -1) {
                const int j = tid + k * NT;
                float num = __fsub_rn(djv[k], dmin);
                float q   = __fdiv_rn(num, s);
                float lc  = ((int)sm.lbl[j] == cls) ? 0.0f : 1.0f;
                float cost = __fadd_rn(q, lc);
                unsigned long long kk =
                    ((unsigned long long)__float_as_uint(cost) << 32) | (unsigned)j;
                key = u64min(key, kk);
            }
        }
#pragma unroll
        for (int o = 16; o; o >>= 1)
            key = u64min(key, __shfl_xor_sync(0xffffffffu, key, o));
        if (lane == 0) sm.pB[buf][wid] = key;
        __syncthreads();   // sync 2

        key = sm.pB[buf][lane];
#pragma unroll
        for (int o = 16; o; o >>= 1)
            key = u64min(key, __shfl_xor_sync(0xffffffffu, key, o));
        const int ci = (int)(unsigned)(key & 0xffffffffu);

        // new-cluster decision (redundant per-thread; identical inputs)
        const float m   = sm.amdm[cls];
        const float hh  = sm.amdh[cls];
        const float r2c = sm.r2[cls];
        float dx = __fsub_rn(pcx, sm.px[ci]);
        float dy = __fsub_rn(pcy, sm.py[ci]);
        float dz = __fsub_rn(pcz, sm.pz[ci]);
        bool nc1 = (fabsf(dx) > m) || (fabsf(dy) > m) || (fabsf(dz) > hh);
        float nd = __fsqrt_rn(__fadd_rn(__fadd_rn(__fmul_rn(dx, dx), __fmul_rn(dy, dy)),
                                        __fmul_rn(dz, dz)));
        float ex = __fsub_rn(ccx, sm.px[ci]);
        float ey = __fsub_rn(ccy, sm.py[ci]);
        float ez = __fsub_rn(ccz, sm.pz[ci]);
        float ndc = __fsqrt_rn(__fadd_rn(__fadd_rn(__fmul_rn(ex, ex), __fmul_rn(ey, ey)),
                                         __fmul_rn(ez, ez)));
        bool newc = nc1 || (amax < ANGLE_THR) || ((int)sm.lbl[ci] != cls)
                        || (nd > r2c) || (ndc > r2c);
        lab += newc ? 1 : 0;
        sm.dl[ci] = (short)lab;
        cur = ci;
    }
    __syncthreads();

    // ---- cluster stats ----
    const int nc = lab;   // num_clusters = dl.max(), EXCLUSIVE
    for (int c = tid; c < nc; c += NT) {
        int cnt = 0;
        float ax = 0.f, ay = 0.f, az = 0.f;
        for (int j = 0; j < NPTS; ++j) {
            if ((int)sm.dl[j] == c) {
                ++cnt;
                ax = __fadd_rn(ax, sm.px[j]);
                ay = __fadd_rn(ay, sm.py[j]);
                az = __fadd_rn(az, sm.pz[j]);
            }
        }
        g_counts[c] = cnt;
        float cfv = (float)(cnt > 0 ? cnt : 1);
        g_cenx[c] = __fdiv_rn(ax, cfv);
        g_ceny[c] = __fdiv_rn(ay, cfv);
        g_cenz[c] = __fdiv_rn(az, cfv);
    }
    __syncthreads();

    // ---- stable descending-count rank sort ----
    for (int i = tid; i < nc; i += NT) {
        int ci_ = g_counts[i];
        int r = 0;
        for (int j = 0; j < nc; ++j) {
            int cj = g_counts[j];
            r += (cj > ci_) || (cj == ci_ && j < i);
        }
        g_order[r] = i;
        g_keep[r]  = 1;
    }
    __syncthreads();

    // ---- greedy merge scan ----
    for (int i = 0; i < nc; ++i) {
        if (g_keep[i]) {
            const int idx = g_order[i];
            const int mcls = g_cc[idx];
            const float r2c = sm.r2[mcls];
            const float cx = g_cenx[idx], cy = g_ceny[idx], cz = g_cenz[idx];
            for (int p = i + 1 + tid; p < nc; p += NT) {
                if (g_keep[p]) {
                    int o = g_order[p];
                    if (g_cc[o] == mcls) {
                        float dx = __fsub_rn(g_cenx[o], cx);
                        float dy = __fsub_rn(g_ceny[o], cy);
                        float dz = __fsub_rn(g_cenz[o], cz);
                        float dd = __fsqrt_rn(__fadd_rn(
                            __fadd_rn(__fmul_rn(dx, dx), __fmul_rn(dy, dy)),
                            __fmul_rn(dz, dz)));
                        if (dd < r2c) {
                            g_keep[p] = 0;
                            g_cmap[o] = idx;
                        }
                    }
                }
            }
        }
        __syncthreads();
    }

    // ---- final relabel: OUTPUT AS FLOAT32 (the __output__ dtype) ----
    for (int j = tid; j < NPTS; j += NT)
        out[j] = (float)g_cmap[(int)sm.dl[j]];
}

extern "C" void kernel_launch(void* const* d_in, const int* in_sizes, int n_in,
                              void* d_out, int out_size) {
    // Route inputs by element count: points=9216 f32, labels=3072 i32, anchors=30 f32
    const float* pts = nullptr;
    const int*   lbl = nullptr;
    const float* anc = nullptr;
    for (int i = 0; i < n_in; ++i) {
        if (in_sizes[i] == NPTS * 3)      pts = (const float*)d_in[i];
        else if (in_sizes[i] == NPTS)     lbl = (const int*)d_in[i];
        else if (in_sizes[i] == NCLS * 3) anc = (const float*)d_in[i];
    }
    float* out = (float*)d_out;

    dist_kernel<<<NPTS, 256>>>(pts);
    cluster_kernel<<<1, NT>>>(pts, lbl, anc, out);
}

// round 11
// speedup vs baseline: 1.0524x; 1.0524x over previous
#include <cuda_runtime.h>
#include <math.h>
#include <stdint.h>

#define NPTS 3072
#define NT   1024
#define EPB  3          // NPTS / NT
#define NCLS 10

static_assert(NT * EPB == NPTS, "partition");

// 3072x3072 fp32 distance matrix, angle-bit packed into sign (37.7MB, L2-resident)
__device__ unsigned g_D[(size_t)NPTS * NPTS];

// cold merge-phase state (device globals)
__device__ int   g_cc[NPTS];
__device__ int   g_counts[NPTS];
__device__ float g_cenx[NPTS], g_ceny[NPTS], g_cenz[NPTS];
__device__ int   g_order[NPTS];
__device__ int   g_cmap[NPTS];
__device__ int   g_keep[NPTS];

// JAX acos: acos(x) = x!=-1 ? 2*atan2(sqrt(1-x*x), 1+x) : pi
__device__ __forceinline__ float xla_acosf(float v) {
    const float PI_F = __int_as_float(0x40490fdb);
    if (v == -1.0f) return PI_F;
    float s = __fsqrt_rn(__fsub_rn(1.0f, __fmul_rn(v, v)));
    float c = __fadd_rn(1.0f, v);
    return __fmul_rn(2.0f, atan2f(s, c));
}

// ---------------- Kernel 1: pairwise distance + angle-bit precompute ----------------
__global__ void dist_kernel(const float* __restrict__ pts) {
    const float ANGLE_THR = __int_as_float(0x3fc90fdb);   // fp32(pi/2)
    int i = blockIdx.x;
    float xi = pts[3 * i + 0], yi = pts[3 * i + 1], zi = pts[3 * i + 2];
    float npc = __fsqrt_rn(__fadd_rn(
        __fadd_rn(__fmul_rn(xi, xi), __fmul_rn(yi, yi)), __fmul_rn(zi, zi)));
    for (int j = threadIdx.x; j < NPTS; j += blockDim.x) {
        float dx = __fsub_rn(pts[3 * j + 0], xi);
        float dy = __fsub_rn(pts[3 * j + 1], yi);
        float dz = __fsub_rn(pts[3 * j + 2], zi);
        float s2 = __fadd_rn(__fadd_rn(__fmul_rn(dx, dx), __fmul_rn(dy, dy)),
                             __fmul_rn(dz, dz));
        float d  = __fsqrt_rn(s2);
        // angle(i, j): dot = -(p_i . (p_j - p_i)), denom = |p_i|*d + 1e-8
        float dot = __fadd_rn(__fadd_rn(__fmul_rn(xi, dx), __fmul_rn(yi, dy)),
                              __fmul_rn(zi, dz));
        dot = -dot;
        float den = __fadd_rn(__fmul_rn(npc, d), 1e-8f);
        float v = __fdiv_rn(dot, den);
        v = fminf(fmaxf(v, -1.0f), 1.0f);
        unsigned bit = (xla_acosf(v) >= ANGLE_THR) ? 0x80000000u : 0u;
        g_D[(size_t)i * NPTS + j] = __float_as_uint(d) | bit;
    }
}

// ---------------- static-smem hot state ----------------
struct SMh {
    unsigned long long pB[2][32];      // 512
    float px[NPTS], py[NPTS], pz[NPTS];// 36864
    float pA[2][6][32];                // 1536  (dmin,dmax,sx,sy,sz,cf)
    int   pAi[2][32];                  // 256   (angle-bit OR partials)
    short dl[NPTS];                    // 6144
    signed char lbl[NPTS];             // 3072
    float amdm[NCLS], amdh[NCLS], r2[NCLS]; // 120
};

__device__ __forceinline__ unsigned long long u64min(unsigned long long a,
                                                     unsigned long long b) {
    return a < b ? a : b;
}

__global__ __launch_bounds__(NT, 1)
void cluster_kernel(const float* __restrict__ pts, const int* __restrict__ lblg,
                    const float* __restrict__ anc, float* __restrict__ out) {
    __shared__ SMh sm;
    const int tid  = threadIdx.x;
    const int lane = tid & 31;
    const int wid  = tid >> 5;
    const float INF  = __int_as_float(0x7f800000);
    const float NINF = __int_as_float(0xff800000);

    // ---- init state ----
    for (int j = tid; j < NPTS; j += NT) {
        sm.px[j] = pts[3 * j + 0];
        sm.py[j] = pts[3 * j + 1];
        sm.pz[j] = pts[3 * j + 2];
        sm.lbl[j] = (signed char)lblg[j];
        sm.dl[j]  = (j == 0) ? 0 : -1;
        g_cmap[j] = j;
    }
    if (tid < NCLS) {
        float l = anc[3 * tid + 0], w = anc[3 * tid + 1], h = anc[3 * tid + 2];
        sm.amdm[tid] = fmaxf(l, w);
        sm.amdh[tid] = h;
        float n2 = __fadd_rn(__fadd_rn(__fmul_rn(l, l), __fmul_rn(w, w)),
                             __fmul_rn(h, h));
        sm.r2[tid] = __fdiv_rn(__fsqrt_rn(n2), 2.0f);
    }
    __syncthreads();

    if (tid == 0) g_cc[0] = (int)sm.lbl[0];   // write-only, off critical path

    // ---- main sequential greedy loop: 3071 steps ----
    int cur = 0, lab = 0;
    for (int step = 0; step < NPTS - 1; ++step) {
        const int buf = step & 1;
        const int cls = (int)sm.lbl[cur];
        const float pcx = sm.px[cur], pcy = sm.py[cur], pcz = sm.pz[cur];
        const unsigned* Drow = g_D + (size_t)cur * NPTS;

        // Phase A: loads + partial (dmin, dmax, centre-sum, count, angle-bit OR)
        float djv[EPB];
        int   stv[EPB];
        float dmin = INF, dmax = NINF;
        float sx = 0.f, sy = 0.f, sz = 0.f, cf = 0.f;
        int aany = 0;
#pragma unroll
        for (int k = 0; k < EPB; ++k) {
            const int j = tid + k * NT;
            unsigned ub = __ldg(Drow + j);
            float d  = __int_as_float(ub & 0x7fffffffu);
            int   ab = (int)(ub >> 31);
            int   dv = (int)sm.dl[j];
            djv[k] = d;
            stv[k] = dv;
            if (dv == -1) { dmin = fminf(dmin, d); dmax = fmaxf(dmax, d); }
            if (dv == lab) {
                sx = __fadd_rn(sx, sm.px[j]);
                sy = __fadd_rn(sy, sm.py[j]);
                sz = __fadd_rn(sz, sm.pz[j]);
                cf = __fadd_rn(cf, 1.0f);
                aany |= ab;
            }
        }
#pragma unroll
        for (int o = 16; o; o >>= 1) {
            dmin = fminf(dmin, __shfl_xor_sync(0xffffffffu, dmin, o));
            dmax = fmaxf(dmax, __shfl_xor_sync(0xffffffffu, dmax, o));
            aany |= __shfl_xor_sync(0xffffffffu, aany, o);
            sx   = __fadd_rn(sx, __shfl_xor_sync(0xffffffffu, sx, o));
            sy   = __fadd_rn(sy, __shfl_xor_sync(0xffffffffu, sy, o));
            sz   = __fadd_rn(sz, __shfl_xor_sync(0xffffffffu, sz, o));
            cf   = __fadd_rn(cf, __shfl_xor_sync(0xffffffffu, cf, o));
        }
        if (lane == 0) {
            sm.pA[buf][0][wid] = dmin; sm.pA[buf][1][wid] = dmax;
            sm.pA[buf][2][wid] = sx;   sm.pA[buf][3][wid] = sy;
            sm.pA[buf][4][wid] = sz;   sm.pA[buf][5][wid] = cf;
            sm.pAi[buf][wid]   = aany;
        }
        __syncthreads();   // sync 1

        // cross-warp reduce ONLY what phase B needs (dmin, dmax, aany)
        dmin = sm.pA[buf][0][lane]; dmax = sm.pA[buf][1][lane];
        aany = sm.pAi[buf][lane];
#pragma unroll
        for (int o = 16; o; o >>= 1) {
            dmin = fminf(dmin, __shfl_xor_sync(0xffffffffu, dmin, o));
            dmax = fmaxf(dmax, __shfl_xor_sync(0xffffffffu, dmax, o));
            aany |= __shfl_xor_sync(0xffffffffu, aany, o);
        }
        const float s = __fadd_rn(__fsub_rn(dmax, dmin), 1e-8f);

        // Phase B: argmin over unvisited of (dcost + lcost), first-index ties
        unsigned long long key = ~0ull;
#pragma unroll
        for (int k = 0; k < EPB; ++k) {
            if (stv[k] == -1) {
                const int j = tid + k * NT;
                float num = __fsub_rn(djv[k], dmin);
                float q   = __fdiv_rn(num, s);
                float lc  = ((int)sm.lbl[j] == cls) ? 0.0f : 1.0f;
                float cost = __fadd_rn(q, lc);
                unsigned long long kk =
                    ((unsigned long long)__float_as_uint(cost) << 32) | (unsigned)j;
                key = u64min(key, kk);
            }
        }
#pragma unroll
        for (int o = 16; o; o >>= 1)
            key = u64min(key, __shfl_xor_sync(0xffffffffu, key, o));
        if (lane == 0) sm.pB[buf][wid] = key;
        __syncthreads();   // sync 2

        key = sm.pB[buf][lane];
        // deferred cross-warp centre reduce (identical op order as before)
        sx = sm.pA[buf][2][lane]; sy = sm.pA[buf][3][lane];
        sz = sm.pA[buf][4][lane]; cf = sm.pA[buf][5][lane];
#pragma unroll
        for (int o = 16; o; o >>= 1) {
            key = u64min(key, __shfl_xor_sync(0xffffffffu, key, o));
            sx  = __fadd_rn(sx, __shfl_xor_sync(0xffffffffu, sx, o));
            sy  = __fadd_rn(sy, __shfl_xor_sync(0xffffffffu, sy, o));
            sz  = __fadd_rn(sz, __shfl_xor_sync(0xffffffffu, sz, o));
            cf  = __fadd_rn(cf, __shfl_xor_sync(0xffffffffu, cf, o));
        }
        const int ci = (int)(unsigned)(key & 0xffffffffu);
        const float ccx = __fdiv_rn(sx, cf);
        const float ccy = __fdiv_rn(sy, cf);
        const float ccz = __fdiv_rn(sz, cf);

        // new-cluster decision (redundant per-thread; identical inputs)
        const float m   = sm.amdm[cls];
        const float hh  = sm.amdh[cls];
        const float r2c = sm.r2[cls];
        float dx = __fsub_rn(pcx, sm.px[ci]);
        float dy = __fsub_rn(pcy, sm.py[ci]);
        float dz = __fsub_rn(pcz, sm.pz[ci]);
        bool nc1 = (fabsf(dx) > m) || (fabsf(dy) > m) || (fabsf(dz) > hh);
        float nd = __fsqrt_rn(__fadd_rn(__fadd_rn(__fmul_rn(dx, dx), __fmul_rn(dy, dy)),
                                        __fmul_rn(dz, dz)));
        float ex = __fsub_rn(ccx, sm.px[ci]);
        float ey = __fsub_rn(ccy, sm.py[ci]);
        float ez = __fsub_rn(ccz, sm.pz[ci]);
        float ndc = __fsqrt_rn(__fadd_rn(__fadd_rn(__fmul_rn(ex, ex), __fmul_rn(ey, ey)),
                                         __fmul_rn(ez, ez)));
        bool newc = nc1 || (!aany) || ((int)sm.lbl[ci] != cls)
                        || (nd > r2c) || (ndc > r2c);
        lab += newc ? 1 : 0;
        sm.dl[ci] = (short)lab;
        if (tid == 0 && newc) g_cc[lab] = (int)sm.lbl[ci];   // write-only
        cur = ci;
    }
    __syncthreads();

    // ---- cluster stats ----
    const int nc = lab;   // num_clusters = dl.max(), EXCLUSIVE
    for (int c = tid; c < nc; c += NT) {
        int cnt = 0;
        float ax = 0.f, ay = 0.f, az = 0.f;
        for (int j = 0; j < NPTS; ++j) {
            if ((int)sm.dl[j] == c) {
                ++cnt;
                ax = __fadd_rn(ax, sm.px[j]);
                ay = __fadd_rn(ay, sm.py[j]);
                az = __fadd_rn(az, sm.pz[j]);
            }
        }
        g_counts[c] = cnt;
        float cfv = (float)(cnt > 0 ? cnt : 1);
        g_cenx[c] = __fdiv_rn(ax, cfv);
        g_ceny[c] = __fdiv_rn(ay, cfv);
        g_cenz[c] = __fdiv_rn(az, cfv);
    }
    __syncthreads();

    // ---- stable descending-count rank sort ----
    for (int i = tid; i < nc; i += NT) {
        int ci_ = g_counts[i];
        int r = 0;
        for (int j = 0; j < nc; ++j) {
            int cj = g_counts[j];
            r += (cj > ci_) || (cj == ci_ && j < i);
        }
        g_order[r] = i;
        g_keep[r]  = 1;
    }
    __syncthreads();

    // ---- greedy merge scan ----
    for (int i = 0; i < nc; ++i) {
        if (g_keep[i]) {
            const int idx = g_order[i];
            const int mcls = g_cc[idx];
            const float r2c = sm.r2[mcls];
            const float cx = g_cenx[idx], cy = g_ceny[idx], cz = g_cenz[idx];
            for (int p = i + 1 + tid; p < nc; p += NT) {
                if (g_keep[p]) {
                    int o = g_order[p];
                    if (g_cc[o] == mcls) {
                        float dx = __fsub_rn(g_cenx[o], cx);
                        float dy = __fsub_rn(g_ceny[o], cy);
                        float dz = __fsub_rn(g_cenz[o], cz);
                        float dd = __fsqrt_rn(__fadd_rn(
                            __fadd_rn(__fmul_rn(dx, dx), __fmul_rn(dy, dy)),
                            __fmul_rn(dz, dz)));
                        if (dd < r2c) {
                            g_keep[p] = 0;
                            g_cmap[o] = idx;
                        }
                    }
                }
            }
        }
        __syncthreads();
    }

    // ---- final relabel (float32 output dtype) ----
    for (int j = tid; j < NPTS; j += NT)
        out[j] = (float)g_cmap[(int)sm.dl[j]];
}

extern "C" void kernel_launch(void* const* d_in, const int* in_sizes, int n_in,
                              void* d_out, int out_size) {
    // Route inputs by element count: points=9216 f32, labels=3072 i32, anchors=30 f32
    const float* pts = nullptr;
    const int*   lbl = nullptr;
    const float* anc = nullptr;
    for (int i = 0; i < n_in; ++i) {
        if (in_sizes[i] == NPTS * 3)      pts = (const float*)d_in[i];
        else if (in_sizes[i] == NPTS)     lbl = (const int*)d_in[i];
        else if (in_sizes[i] == NCLS * 3) anc = (const float*)d_in[i];
    }
    float* out = (float*)d_out;

    dist_kernel<<<NPTS, 256>>>(pts);
    cluster_kernel<<<1, NT>>>(pts, lbl, anc, out);
}

// round 12
// speedup vs baseline: 1.3882x; 1.3191x over previous
#include <cuda_runtime.h>
#include <math.h>
#include <stdint.h>

#define NPTS 3072
#define NT   256
#define EPB  12         // NPTS / NT
#define NWARP (NT/32)   // 8
#define NCLS 10

static_assert(NT * EPB == NPTS, "partition");

// 3072x3072 fp32 distance matrix, angle-bit packed into sign (37.7MB, L2-resident)
__device__ unsigned g_D[(size_t)NPTS * NPTS];

// cold merge-phase state (device globals)
__device__ int   g_cc[NPTS];
__device__ int   g_counts[NPTS];
__device__ float g_cenx[NPTS], g_ceny[NPTS], g_cenz[NPTS];
__device__ int   g_order[NPTS];
__device__ int   g_cmap[NPTS];
__device__ int   g_keep[NPTS];

// JAX acos: acos(x) = x!=-1 ? 2*atan2(sqrt(1-x*x), 1+x) : pi
__device__ __forceinline__ float xla_acosf(float v) {
    const float PI_F = __int_as_float(0x40490fdb);
    if (v == -1.0f) return PI_F;
    float s = __fsqrt_rn(__fsub_rn(1.0f, __fmul_rn(v, v)));
    float c = __fadd_rn(1.0f, v);
    return __fmul_rn(2.0f, atan2f(s, c));
}

// ---------------- Kernel 1: pairwise distance + angle-bit precompute ----------------
__global__ void dist_kernel(const float* __restrict__ pts) {
    const float ANGLE_THR = __int_as_float(0x3fc90fdb);   // fp32(pi/2)
    int i = blockIdx.x;
    float xi = pts[3 * i + 0], yi = pts[3 * i + 1], zi = pts[3 * i + 2];
    float npc = __fsqrt_rn(__fadd_rn(
        __fadd_rn(__fmul_rn(xi, xi), __fmul_rn(yi, yi)), __fmul_rn(zi, zi)));
    for (int j = threadIdx.x; j < NPTS; j += blockDim.x) {
        float dx = __fsub_rn(pts[3 * j + 0], xi);
        float dy = __fsub_rn(pts[3 * j + 1], yi);
        float dz = __fsub_rn(pts[3 * j + 2], zi);
        float s2 = __fadd_rn(__fadd_rn(__fmul_rn(dx, dx), __fmul_rn(dy, dy)),
                             __fmul_rn(dz, dz));
        float d  = __fsqrt_rn(s2);
        float dot = __fadd_rn(__fadd_rn(__fmul_rn(xi, dx), __fmul_rn(yi, dy)),
                              __fmul_rn(zi, dz));
        dot = -dot;
        float den = __fadd_rn(__fmul_rn(npc, d), 1e-8f);
        float v = __fdiv_rn(dot, den);
        v = fminf(fmaxf(v, -1.0f), 1.0f);
        // acos(v) >= pi/2 certainly holds for v <= -1e-4 and certainly fails for
        // v >= 1e-4 (atan2f err <= 3 ulp << 1e-4 acos deviation); exact path near 0.
        unsigned bit;
        if (v <= -1e-4f)      bit = 0x80000000u;
        else if (v >= 1e-4f)  bit = 0u;
        else bit = (xla_acosf(v) >= ANGLE_THR) ? 0x80000000u : 0u;
        g_D[(size_t)i * NPTS + j] = __float_as_uint(d) | bit;
    }
}

// ---------------- static-smem hot state ----------------
struct SMh {
    unsigned long long pB[2][NWARP];   // phase-B warp partials
    float px[NPTS], py[NPTS], pz[NPTS];
    float pA[2][6][NWARP];             // dmin,dmax,sx,sy,sz,cf
    int   pAi[2][NWARP];               // angle-bit OR partials
    short dl[NPTS];
    signed char lbl[NPTS];
    float amdm[NCLS], amdh[NCLS], r2[NCLS];
};

__device__ __forceinline__ unsigned long long u64min(unsigned long long a,
                                                     unsigned long long b) {
    return a < b ? a : b;
}

__global__ __launch_bounds__(NT, 1)
void cluster_kernel(const float* __restrict__ pts, const int* __restrict__ lblg,
                    const float* __restrict__ anc, float* __restrict__ out) {
    __shared__ SMh sm;
    const int tid  = threadIdx.x;
    const int lane = tid & 31;
    const int wid  = tid >> 5;
    const float INF  = __int_as_float(0x7f800000);
    const float NINF = __int_as_float(0xff800000);

    // ---- init state ----
    for (int j = tid; j < NPTS; j += NT) {
        sm.px[j] = pts[3 * j + 0];
        sm.py[j] = pts[3 * j + 1];
        sm.pz[j] = pts[3 * j + 2];
        sm.lbl[j] = (signed char)lblg[j];
        sm.dl[j]  = (j == 0) ? 0 : -1;
        g_cmap[j] = j;
    }
    if (tid < NCLS) {
        float l = anc[3 * tid + 0], w = anc[3 * tid + 1], h = anc[3 * tid + 2];
        sm.amdm[tid] = fmaxf(l, w);
        sm.amdh[tid] = h;
        float n2 = __fadd_rn(__fadd_rn(__fmul_rn(l, l), __fmul_rn(w, w)),
                             __fmul_rn(h, h));
        sm.r2[tid] = __fdiv_rn(__fsqrt_rn(n2), 2.0f);
    }
    __syncthreads();

    if (tid == 0) g_cc[0] = (int)sm.lbl[0];

    // static per-thread labels -> registers (j = tid*EPB + k, contiguous)
    int lblv[EPB];
#pragma unroll
    for (int k = 0; k < EPB; ++k) lblv[k] = (int)sm.lbl[tid * EPB + k];

    // ---- main sequential greedy loop: 3071 steps ----
    int cur = 0, lab = 0;
    for (int step = 0; step < NPTS - 1; ++step) {
        const int buf = step & 1;
        const int cls = (int)sm.lbl[cur];
        const float pcx = sm.px[cur], pcy = sm.py[cur], pcz = sm.pz[cur];

        // vectorized loads: 12 uints = 3 x LDG.128 (row 16B-aligned)
        const uint4* Drow4 =
            reinterpret_cast<const uint4*>(g_D + (size_t)cur * NPTS) + tid * 3;
        uint4 u0 = __ldg(Drow4 + 0);
        uint4 u1 = __ldg(Drow4 + 1);
        uint4 u2 = __ldg(Drow4 + 2);
        unsigned ub[EPB] = {u0.x, u0.y, u0.z, u0.w, u1.x, u1.y, u1.z, u1.w,
                            u2.x, u2.y, u2.z, u2.w};

        // dl: 12 shorts = 3 x LDS.64 (8B-aligned)
        const uint2* dlv = reinterpret_cast<const uint2*>(sm.dl) + tid * 3;
        uint2 w0 = dlv[0], w1 = dlv[1], w2 = dlv[2];
        unsigned wv[6] = {w0.x, w0.y, w1.x, w1.y, w2.x, w2.y};
        int stv[EPB];
#pragma unroll
        for (int m = 0; m < 6; ++m) {
            stv[2 * m + 0] = (int)((short)(wv[m] & 0xffffu));
            stv[2 * m + 1] = (int)((short)(wv[m] >> 16));
        }

        // Phase A: partial (dmin, dmax, centre-sum, count, angle-bit OR)
        float djv[EPB];
        float dmin = INF, dmax = NINF;
        float sx = 0.f, sy = 0.f, sz = 0.f, cf = 0.f;
        int aany = 0;
#pragma unroll
        for (int k = 0; k < EPB; ++k) {
            float d = __int_as_float(ub[k] & 0x7fffffffu);
            djv[k] = d;
            if (stv[k] == -1) { dmin = fminf(dmin, d); dmax = fmaxf(dmax, d); }
            if (stv[k] == lab) {
                const int j = tid * EPB + k;
                sx = __fadd_rn(sx, sm.px[j]);
                sy = __fadd_rn(sy, sm.py[j]);
                sz = __fadd_rn(sz, sm.pz[j]);
                cf = __fadd_rn(cf, 1.0f);
                aany |= (int)(ub[k] >> 31);
            }
        }
#pragma unroll
        for (int o = 16; o; o >>= 1) {
            dmin = fminf(dmin, __shfl_xor_sync(0xffffffffu, dmin, o));
            dmax = fmaxf(dmax, __shfl_xor_sync(0xffffffffu, dmax, o));
            aany |= __shfl_xor_sync(0xffffffffu, aany, o);
            sx   = __fadd_rn(sx, __shfl_xor_sync(0xffffffffu, sx, o));
            sy   = __fadd_rn(sy, __shfl_xor_sync(0xffffffffu, sy, o));
            sz   = __fadd_rn(sz, __shfl_xor_sync(0xffffffffu, sz, o));
            cf   = __fadd_rn(cf, __shfl_xor_sync(0xffffffffu, cf, o));
        }
        if (lane == 0) {
            sm.pA[buf][0][wid] = dmin; sm.pA[buf][1][wid] = dmax;
            sm.pA[buf][2][wid] = sx;   sm.pA[buf][3][wid] = sy;
            sm.pA[buf][4][wid] = sz;   sm.pA[buf][5][wid] = cf;
            sm.pAi[buf][wid]   = aany;
        }
        __syncthreads();   // sync 1

        // cross-warp reduce (8 partials; every lane reads lane&7, 3 rounds)
        {
            const int l8 = lane & (NWARP - 1);
            dmin = sm.pA[buf][0][l8]; dmax = sm.pA[buf][1][l8];
            aany = sm.pAi[buf][l8];
#pragma unroll
            for (int o = NWARP / 2; o; o >>= 1) {
                dmin = fminf(dmin, __shfl_xor_sync(0xffffffffu, dmin, o));
                dmax = fmaxf(dmax, __shfl_xor_sync(0xffffffffu, dmax, o));
                aany |= __shfl_xor_sync(0xffffffffu, aany, o);
            }
        }
        const float s    = __fadd_rn(__fsub_rn(dmax, dmin), 1e-8f);
        const float y    = __frcp_rn(s);   // correctly-rounded reciprocal
        const float negs = -s;

        // Phase B: argmin over unvisited of (dcost + lcost), first-index ties.
        // Markstein division == div.rn.f32 bitwise for these (normal) operands.
        unsigned long long key = ~0ull;
#pragma unroll
        for (int k = 0; k < EPB; ++k) {
            if (stv[k] == -1) {
                const int j = tid * EPB + k;
                float num = __fsub_rn(djv[k], dmin);
                float q0  = __fmul_rn(num, y);
                float rem = __fmaf_rn(negs, q0, num);
                float q   = __fmaf_rn(rem, y, q0);
                float lc  = (lblv[k] == cls) ? 0.0f : 1.0f;
                float cost = __fadd_rn(q, lc);
                unsigned long long kk =
                    ((unsigned long long)__float_as_uint(cost) << 32) | (unsigned)j;
                key = u64min(key, kk);
            }
        }
#pragma unroll
        for (int o = 16; o; o >>= 1)
            key = u64min(key, __shfl_xor_sync(0xffffffffu, key, o));
        if (lane == 0) sm.pB[buf][wid] = key;
        __syncthreads();   // sync 2

        {
            const int l8 = lane & (NWARP - 1);
            key = sm.pB[buf][l8];
            sx = sm.pA[buf][2][l8]; sy = sm.pA[buf][3][l8];
            sz = sm.pA[buf][4][l8]; cf = sm.pA[buf][5][l8];
#pragma unroll
            for (int o = NWARP / 2; o; o >>= 1) {
                key = u64min(key, __shfl_xor_sync(0xffffffffu, key, o));
                sx  = __fadd_rn(sx, __shfl_xor_sync(0xffffffffu, sx, o));
                sy  = __fadd_rn(sy, __shfl_xor_sync(0xffffffffu, sy, o));
                sz  = __fadd_rn(sz, __shfl_xor_sync(0xffffffffu, sz, o));
                cf  = __fadd_rn(cf, __shfl_xor_sync(0xffffffffu, cf, o));
            }
        }
        const int ci = (int)(unsigned)(key & 0xffffffffu);
        const float ccx = __fdiv_rn(sx, cf);
        const float ccy = __fdiv_rn(sy, cf);
        const float ccz = __fdiv_rn(sz, cf);

        // new-cluster decision (redundant per-thread; identical inputs)
        const float m   = sm.amdm[cls];
        const float hh  = sm.amdh[cls];
        const float r2c = sm.r2[cls];
        float dx = __fsub_rn(pcx, sm.px[ci]);
        float dy = __fsub_rn(pcy, sm.py[ci]);
        float dz = __fsub_rn(pcz, sm.pz[ci]);
        bool nc1 = (fabsf(dx) > m) || (fabsf(dy) > m) || (fabsf(dz) > hh);
        float nd = __fsqrt_rn(__fadd_rn(__fadd_rn(__fmul_rn(dx, dx), __fmul_rn(dy, dy)),
                                        __fmul_rn(dz, dz)));
        float ex = __fsub_rn(ccx, sm.px[ci]);
        float ey = __fsub_rn(ccy, sm.py[ci]);
        float ez = __fsub_rn(ccz, sm.pz[ci]);
        float ndc = __fsqrt_rn(__fadd_rn(__fadd_rn(__fmul_rn(ex, ex), __fmul_rn(ey, ey)),
                                         __fmul_rn(ez, ez)));
        bool newc = nc1 || (!aany) || ((int)sm.lbl[ci] != cls)
                        || (nd > r2c) || (ndc > r2c);
        lab += newc ? 1 : 0;
        sm.dl[ci] = (short)lab;
        if (tid == 0 && newc) g_cc[lab] = (int)sm.lbl[ci];
        cur = ci;
    }
    __syncthreads();

    // ---- cluster stats (serial index-order sums, unchanged from validated) ----
    const int nc = lab;   // num_clusters = dl.max(), EXCLUSIVE
    for (int c = tid; c < nc; c += NT) {
        int cnt = 0;
        float ax = 0.f, ay = 0.f, az = 0.f;
        for (int j = 0; j < NPTS; ++j) {
            if ((int)sm.dl[j] == c) {
                ++cnt;
                ax = __fadd_rn(ax, sm.px[j]);
                ay = __fadd_rn(ay, sm.py[j]);
                az = __fadd_rn(az, sm.pz[j]);
            }
        }
        g_counts[c] = cnt;
        float cfv = (float)(cnt > 0 ? cnt : 1);
        g_cenx[c] = __fdiv_rn(ax, cfv);
        g_ceny[c] = __fdiv_rn(ay, cfv);
        g_cenz[c] = __fdiv_rn(az, cfv);
    }
    __syncthreads();

    // ---- stable descending-count rank sort ----
    for (int i = tid; i < nc; i += NT) {
        int ci_ = g_counts[i];
        int r = 0;
        for (int j = 0; j < nc; ++j) {
            int cj = g_counts[j];
            r += (cj > ci_) || (cj == ci_ && j < i);
        }
        g_order[r] = i;
        g_keep[r]  = 1;
    }
    __syncthreads();

    // ---- greedy merge scan ----
    for (int i = 0; i < nc; ++i) {
        if (g_keep[i]) {
            const int idx = g_order[i];
            const int mcls = g_cc[idx];
            const float r2c = sm.r2[mcls];
            const float cx = g_cenx[idx], cy = g_ceny[idx], cz = g_cenz[idx];
            for (int p = i + 1 + tid; p < nc; p += NT) {
                if (g_keep[p]) {
                    int o = g_order[p];
                    if (g_cc[o] == mcls) {
                        float dx = __fsub_rn(g_cenx[o], cx);
                        float dy = __fsub_rn(g_ceny[o], cy);
                        float dz = __fsub_rn(g_cenz[o], cz);
                        float dd = __fsqrt_rn(__fadd_rn(
                            __fadd_rn(__fmul_rn(dx, dx), __fmul_rn(dy, dy)),
                            __fmul_rn(dz, dz)));
                        if (dd < r2c) {
                            g_keep[p] = 0;
                            g_cmap[o] = idx;
                        }
                    }
                }
            }
        }
        __syncthreads();
    }

    // ---- final relabel (float32 output dtype) ----
    for (int j = tid; j < NPTS; j += NT)
        out[j] = (float)g_cmap[(int)sm.dl[j]];
}

extern "C" void kernel_launch(void* const* d_in, const int* in_sizes, int n_in,
                              void* d_out, int out_size) {
    // Route inputs by element count: points=9216 f32, labels=3072 i32, anchors=30 f32
    const float* pts = nullptr;
    const int*   lbl = nullptr;
    const float* anc = nullptr;
    for (int i = 0; i < n_in; ++i) {
        if (in_sizes[i] == NPTS * 3)      pts = (const float*)d_in[i];
        else if (in_sizes[i] == NPTS)     lbl = (const int*)d_in[i];
        else if (in_sizes[i] == NCLS * 3) anc = (const float*)d_in[i];
    }
    float* out = (float*)d_out;

    dist_kernel<<<NPTS, 256>>>(pts);
    cluster_kernel<<<1, NT>>>(pts, lbl, anc, out);
}

// round 14
// speedup vs baseline: 1.5133x; 1.0901x over previous
#include <cuda_runtime.h>
#include <math.h>
#include <stdint.h>

#define NPTS 3072
#define NT   256
#define EPB  12         // NPTS / NT
#define NWARP (NT/32)   // 8
#define NCLS 10

static_assert(NT * EPB == NPTS, "partition");

// 3072x3072 fp32 distance matrix, angle-bit packed into sign (37.7MB, L2-resident)
__device__ unsigned g_D[(size_t)NPTS * NPTS];

// cold merge-phase state (device globals)
__device__ int   g_cc[NPTS];
__device__ int   g_counts[NPTS];
__device__ float g_cenx[NPTS], g_ceny[NPTS], g_cenz[NPTS];
__device__ int   g_order[NPTS];
__device__ int   g_cmap[NPTS];
__device__ int   g_keep[NPTS];

// JAX acos: acos(x) = x!=-1 ? 2*atan2(sqrt(1-x*x), 1+x) : pi
__device__ __forceinline__ float xla_acosf(float v) {
    const float PI_F = __int_as_float(0x40490fdb);
    if (v == -1.0f) return PI_F;
    float s = __fsqrt_rn(__fsub_rn(1.0f, __fmul_rn(v, v)));
    float c = __fadd_rn(1.0f, v);
    return __fmul_rn(2.0f, atan2f(s, c));
}

// ---------------- Kernel 1: pairwise distance + angle-bit precompute ----------------
__global__ void dist_kernel(const float* __restrict__ pts) {
    const float ANGLE_THR = __int_as_float(0x3fc90fdb);   // fp32(pi/2)
    int i = blockIdx.x;
    float xi = pts[3 * i + 0], yi = pts[3 * i + 1], zi = pts[3 * i + 2];
    float npc = __fsqrt_rn(__fadd_rn(
        __fadd_rn(__fmul_rn(xi, xi), __fmul_rn(yi, yi)), __fmul_rn(zi, zi)));
    for (int j = threadIdx.x; j < NPTS; j += blockDim.x) {
        float dx = __fsub_rn(pts[3 * j + 0], xi);
        float dy = __fsub_rn(pts[3 * j + 1], yi);
        float dz = __fsub_rn(pts[3 * j + 2], zi);
        float s2 = __fadd_rn(__fadd_rn(__fmul_rn(dx, dx), __fmul_rn(dy, dy)),
                             __fmul_rn(dz, dz));
        float d  = __fsqrt_rn(s2);
        float dot = __fadd_rn(__fadd_rn(__fmul_rn(xi, dx), __fmul_rn(yi, dy)),
                              __fmul_rn(zi, dz));
        dot = -dot;
        float den = __fadd_rn(__fmul_rn(npc, d), 1e-8f);
        float v = __fdiv_rn(dot, den);
        v = fminf(fmaxf(v, -1.0f), 1.0f);
        // certainty shortcut: |v|>=1e-4 decides acos(v) vs pi/2 without atan2f
        unsigned bit;
        if (v <= -1e-4f)      bit = 0x80000000u;
        else if (v >= 1e-4f)  bit = 0u;
        else bit = (xla_acosf(v) >= ANGLE_THR) ? 0x80000000u : 0u;
        g_D[(size_t)i * NPTS + j] = __float_as_uint(d) | bit;
    }
}

// ---------------- static-smem state ----------------
struct SMh {
    unsigned long long pB[2][NWARP];
    float px[NPTS], py[NPTS], pz[NPTS];
    float pA[2][6][NWARP];             // dmin,dmax,sx,sy,sz,cf
    int   pAi[2][NWARP];               // angle-bit OR partials
    short dl[NPTS];
    signed char lbl[NPTS];
    float amdm[NCLS], amdh[NCLS], r2[NCLS];
};

__device__ __forceinline__ unsigned long long u64min(unsigned long long a,
                                                     unsigned long long b) {
    return a < b ? a : b;
}

__global__ __launch_bounds__(NT, 1)
void cluster_kernel(const float* __restrict__ pts, const int* __restrict__ lblg,
                    const float* __restrict__ anc, float* __restrict__ out) {
    __shared__ SMh sm;
    const int tid  = threadIdx.x;
    const int lane = tid & 31;
    const int wid  = tid >> 5;
    const int jbase = tid * EPB;
    const float INF  = __int_as_float(0x7f800000);
    const float NINF = __int_as_float(0xff800000);

    // ---- init state ----
    for (int j = tid; j < NPTS; j += NT) {
        sm.px[j] = pts[3 * j + 0];
        sm.py[j] = pts[3 * j + 1];
        sm.pz[j] = pts[3 * j + 2];
        sm.lbl[j] = (signed char)lblg[j];
        g_cmap[j] = j;
    }
    if (tid < NCLS) {
        float l = anc[3 * tid + 0], w = anc[3 * tid + 1], h = anc[3 * tid + 2];
        sm.amdm[tid] = fmaxf(l, w);
        sm.amdh[tid] = h;
        float n2 = __fadd_rn(__fadd_rn(__fmul_rn(l, l), __fmul_rn(w, w)),
                             __fmul_rn(h, h));
        sm.r2[tid] = __fdiv_rn(__fsqrt_rn(n2), 2.0f);
    }
    __syncthreads();

    if (tid == 0) g_cc[0] = (int)sm.lbl[0];

    // ---- registerize owned elements: positions, labels, visit status ----
    float rpx[EPB], rpy[EPB], rpz[EPB];
    int   lblv[EPB], stv[EPB];
#pragma unroll
    for (int k = 0; k < EPB; ++k) {
        const int j = jbase + k;
        rpx[k] = sm.px[j]; rpy[k] = sm.py[j]; rpz[k] = sm.pz[j];
        lblv[k] = (int)sm.lbl[j];
        stv[k]  = (j == 0) ? 0 : -1;
    }

    // preload row 0 + step-0 current-point state
    unsigned ub[EPB];
    {
        const uint4* r4 = reinterpret_cast<const uint4*>(g_D) + tid * 3;
        uint4 u0 = __ldg(r4 + 0), u1 = __ldg(r4 + 1), u2 = __ldg(r4 + 2);
        ub[0]=u0.x; ub[1]=u0.y; ub[2]=u0.z; ub[3]=u0.w;
        ub[4]=u1.x; ub[5]=u1.y; ub[6]=u1.z; ub[7]=u1.w;
        ub[8]=u2.x; ub[9]=u2.y; ub[10]=u2.z; ub[11]=u2.w;
    }
    float pcx = sm.px[0], pcy = sm.py[0], pcz = sm.pz[0];
    int   cls = (int)sm.lbl[0];

    // ---- main sequential greedy loop: 3071 steps ----
    int lab = 0;
    for (int step = 0; step < NPTS - 1; ++step) {
        const int buf = step & 1;

        // Phase A (pure registers): dmin/dmax over unvisited; deferred sums over cm
        float djv[EPB];
        float dmin = INF, dmax = NINF;
        float sx = 0.f, sy = 0.f, sz = 0.f, cf = 0.f;
        int aany = 0;
#pragma unroll
        for (int k = 0; k < EPB; ++k) {
            float d = __int_as_float(ub[k] & 0x7fffffffu);
            djv[k] = d;
            if (stv[k] == -1) { dmin = fminf(dmin, d); dmax = fmaxf(dmax, d); }
            if (stv[k] == lab) {
                sx = __fadd_rn(sx, rpx[k]);
                sy = __fadd_rn(sy, rpy[k]);
                sz = __fadd_rn(sz, rpz[k]);
                cf = __fadd_rn(cf, 1.0f);
                aany |= (int)(ub[k] >> 31);
            }
        }
        // pre-bar reduce: ONLY dmin/dmax (short critical chain)
#pragma unroll
        for (int o = 16; o; o >>= 1) {
            dmin = fminf(dmin, __shfl_xor_sync(0xffffffffu, dmin, o));
            dmax = fmaxf(dmax, __shfl_xor_sync(0xffffffffu, dmax, o));
        }
        if (lane == 0) {
            sm.pA[buf][0][wid] = dmin;
            sm.pA[buf][1][wid] = dmax;
        }
        __syncthreads();   // sync 1
        {
            const int l8 = lane & (NWARP - 1);
            dmin = sm.pA[buf][0][l8]; dmax = sm.pA[buf][1][l8];
#pragma unroll
            for (int o = NWARP / 2; o; o >>= 1) {
                dmin = fminf(dmin, __shfl_xor_sync(0xffffffffu, dmin, o));
                dmax = fmaxf(dmax, __shfl_xor_sync(0xffffffffu, dmax, o));
            }
        }
        const float s    = __fadd_rn(__fsub_rn(dmax, dmin), 1e-8f);
        const float y    = __frcp_rn(s);
        const float negs = -s;

        // Phase B: argmin of (dcost + lcost), first-index ties (Markstein div)
        unsigned long long key = ~0ull;
#pragma unroll
        for (int k = 0; k < EPB; ++k) {
            if (stv[k] == -1) {
                float num = __fsub_rn(djv[k], dmin);
                float q0  = __fmul_rn(num, y);
                float rem = __fmaf_rn(negs, q0, num);
                float q   = __fmaf_rn(rem, y, q0);
                float lc  = (lblv[k] == cls) ? 0.0f : 1.0f;
                float cost = __fadd_rn(q, lc);
                unsigned long long kk =
                    ((unsigned long long)__float_as_uint(cost) << 32)
                    | (unsigned)(jbase + k);
                key = u64min(key, kk);
            }
        }
        // warp-reduce key + deferred quantities together
#pragma unroll
        for (int o = 16; o; o >>= 1) {
            key  = u64min(key, __shfl_xor_sync(0xffffffffu, key, o));
            aany |= __shfl_xor_sync(0xffffffffu, aany, o);
            sx   = __fadd_rn(sx, __shfl_xor_sync(0xffffffffu, sx, o));
            sy   = __fadd_rn(sy, __shfl_xor_sync(0xffffffffu, sy, o));
            sz   = __fadd_rn(sz, __shfl_xor_sync(0xffffffffu, sz, o));
            cf   = __fadd_rn(cf, __shfl_xor_sync(0xffffffffu, cf, o));
        }
        if (lane == 0) {
            sm.pB[buf][wid]    = key;
            sm.pA[buf][2][wid] = sx; sm.pA[buf][3][wid] = sy;
            sm.pA[buf][4][wid] = sz; sm.pA[buf][5][wid] = cf;
            sm.pAi[buf][wid]   = aany;
        }
        __syncthreads();   // sync 2
        {
            const int l8 = lane & (NWARP - 1);
            key = sm.pB[buf][l8];
            sx = sm.pA[buf][2][l8]; sy = sm.pA[buf][3][l8];
            sz = sm.pA[buf][4][l8]; cf = sm.pA[buf][5][l8];
            aany = sm.pAi[buf][l8];
#pragma unroll
            for (int o = NWARP / 2; o; o >>= 1) {
                key  = u64min(key, __shfl_xor_sync(0xffffffffu, key, o));
                aany |= __shfl_xor_sync(0xffffffffu, aany, o);
                sx   = __fadd_rn(sx, __shfl_xor_sync(0xffffffffu, sx, o));
                sy   = __fadd_rn(sy, __shfl_xor_sync(0xffffffffu, sy, o));
                sz   = __fadd_rn(sz, __shfl_xor_sync(0xffffffffu, sz, o));
                cf   = __fadd_rn(cf, __shfl_xor_sync(0xffffffffu, cf, o));
            }
        }
        const int ci = (int)(unsigned)(key & 0xffffffffu);

        // prefetch NEXT row immediately (overlaps with decision below)
        uint4 n0, n1, n2;
        {
            const uint4* r4 =
                reinterpret_cast<const uint4*>(g_D + (size_t)ci * NPTS) + tid * 3;
            n0 = __ldg(r4 + 0); n1 = __ldg(r4 + 1); n2 = __ldg(r4 + 2);
        }

        const float ccx = __fdiv_rn(sx, cf);
        const float ccy = __fdiv_rn(sy, cf);
        const float ccz = __fdiv_rn(sz, cf);

        // new-cluster decision (redundant per-thread; identical inputs)
        const float qx = sm.px[ci], qy = sm.py[ci], qz = sm.pz[ci];
        const int   lblci = (int)sm.lbl[ci];
        const float m   = sm.amdm[cls];
        const float hh  = sm.amdh[cls];
        const float r2c = sm.r2[cls];
        float dx = __fsub_rn(pcx, qx);
        float dy = __fsub_rn(pcy, qy);
        float dz = __fsub_rn(pcz, qz);
        bool nc1 = (fabsf(dx) > m) || (fabsf(dy) > m) || (fabsf(dz) > hh);
        float nd = __fsqrt_rn(__fadd_rn(__fadd_rn(__fmul_rn(dx, dx), __fmul_rn(dy, dy)),
                                        __fmul_rn(dz, dz)));
        float ex = __fsub_rn(ccx, qx);
        float ey = __fsub_rn(ccy, qy);
        float ez = __fsub_rn(ccz, qz);
        float ndc = __fsqrt_rn(__fadd_rn(__fadd_rn(__fmul_rn(ex, ex), __fmul_rn(ey, ey)),
                                         __fmul_rn(ez, ez)));
        bool newc = nc1 || (!aany) || (lblci != cls) || (nd > r2c) || (ndc > r2c);
        lab += newc ? 1 : 0;
        if (tid == 0 && newc) g_cc[lab] = lblci;

        // owner updates its register status
        {
            const int kk = ci - jbase;
            if ((unsigned)kk < (unsigned)EPB) stv[kk] = lab;
        }
        // carry over current-point state; unpack prefetched row
        pcx = qx; pcy = qy; pcz = qz; cls = lblci;
        ub[0]=n0.x; ub[1]=n0.y; ub[2]=n0.z; ub[3]=n0.w;
        ub[4]=n1.x; ub[5]=n1.y; ub[6]=n1.z; ub[7]=n1.w;
        ub[8]=n2.x; ub[9]=n2.y; ub[10]=n2.z; ub[11]=n2.w;
    }

    // write back final dl registers to smem for the stats/merge phases
#pragma unroll
    for (int k = 0; k < EPB; ++k) sm.dl[jbase + k] = (short)stv[k];
    __syncthreads();

    // ---- cluster stats (serial index-order sums) ----
    const int nc = lab;   // num_clusters = dl.max(), EXCLUSIVE
    for (int c = tid; c < nc; c += NT) {
        int cnt = 0;
        float ax = 0.f, ay = 0.f, az = 0.f;
        for (int j = 0; j < NPTS; ++j) {
            if ((int)sm.dl[j] == c) {
                ++cnt;
                ax = __fadd_rn(ax, sm.px[j]);
                ay = __fadd_rn(ay, sm.py[j]);
                az = __fadd_rn(az, sm.pz[j]);
            }
        }
        g_counts[c] = cnt;
        float cfv = (float)(cnt > 0 ? cnt : 1);
        g_cenx[c] = __fdiv_rn(ax, cfv);
        g_ceny[c] = __fdiv_rn(ay, cfv);
        g_cenz[c] = __fdiv_rn(az, cfv);
    }
    __syncthreads();

    // ---- stable descending-count rank sort ----
    for (int i = tid; i < nc; i += NT) {
        int ci_ = g_counts[i];
        int r = 0;
        for (int j = 0; j < nc; ++j) {
            int cj = g_counts[j];
            r += (cj > ci_) || (cj == ci_ && j < i);
        }
        g_order[r] = i;
        g_keep[r]  = 1;
    }
    __syncthreads();

    // ---- greedy merge scan ----
    for (int i = 0; i < nc; ++i) {
        if (g_keep[i]) {
            const int idx = g_order[i];
            const int mcls = g_cc[idx];
            const float r2c = sm.r2[mcls];
            const float cx = g_cenx[idx], cy = g_ceny[idx], cz = g_cenz[idx];
            for (int p = i + 1 + tid; p < nc; p += NT) {
                if (g_keep[p]) {
                    int o = g_order[p];
                    if (g_cc[o] == mcls) {
                        float dx = __fsub_rn(g_cenx[o], cx);
                        float dy = __fsub_rn(g_ceny[o], cy);
                        float dz = __fsub_rn(g_cenz[o], cz);
                        float dd = __fsqrt_rn(__fadd_rn(
                            __fadd_rn(__fmul_rn(dx, dx), __fmul_rn(dy, dy)),
                            __fmul_rn(dz, dz)));
                        if (dd < r2c) {
                            g_keep[p] = 0;
                            g_cmap[o] = idx;
                        }
                    }
                }
            }
        }
        __syncthreads();
    }

    // ---- final relabel (float32 output dtype) ----
    for (int j = tid; j < NPTS; j += NT)
        out[j] = (float)g_cmap[(int)sm.dl[j]];
}

extern "C" void kernel_launch(void* const* d_in, const int* in_sizes, int n_in,
                              void* d_out, int out_size) {
    // Route inputs by element count: points=9216 f32, labels=3072 i32, anchors=30 f32
    const float* pts = nullptr;
    const int*   lbl = nullptr;
    const float* anc = nullptr;
    for (int i = 0; i < n_in; ++i) {
        if (in_sizes[i] == NPTS * 3)      pts = (const float*)d_in[i];
        else if (in_sizes[i] == NPTS)     lbl = (const int*)d_in[i];
        else if (in_sizes[i] == NCLS * 3) anc = (const float*)d_in[i];
    }
    float* out = (float*)d_out;

    dist_kernel<<<NPTS, 256>>>(pts);
    cluster_kernel<<<1, NT>>>(pts, lbl, anc, out);
}